// round 7
// baseline (speedup 1.0000x reference)
#include <cuda_runtime.h>
#include <cstdint>

// Problem sizes
#define S    4096
#define II   64
#define H    1024
#define NCTA 128
#define UPC  8        // hidden units per CTA (1 per warp, 8 warps)

// ---------------------------------------------------------------------------
// Device-global scratch (allocation-free rule: __device__ arrays only)
//
// g_hq: double-buffered hidden state, one 8-byte atom per unit:
//       low 32 bits = h value (f32 bits), high 32 bits = step tag.
//       h_t (input of step t) lives in slot t&1 with tag == t.
//
// ALL accesses are st.relaxed.gpu / ld.relaxed.gpu b64: morally-strong
// operations <= 64 bits are single-copy atomic in the PTX memory model.
// Weak (.cg) accesses carry NO atomicity guarantee — that was the R5/R6
// correctness bug (tag could pair with stale h via a torn read).
// Tag+data in one atom => no acquire/release pairing needed.
// ---------------------------------------------------------------------------
__device__ unsigned long long g_hq[2][H];

// ---------------------------------------------------------------------------
// Helpers
// ---------------------------------------------------------------------------
__device__ __forceinline__ unsigned long long pk2(float x, float y) {
    unsigned long long r;
    asm("mov.b64 %0, {%1,%2};" : "=l"(r) : "f"(x), "f"(y));
    return r;
}
__device__ __forceinline__ void upk2(unsigned long long a, float& x, float& y) {
    asm("mov.b64 {%0,%1}, %2;" : "=f"(x), "=f"(y) : "l"(a));
}
__device__ __forceinline__ unsigned long long pk_fu(float x, unsigned t) {
    unsigned long long r;
    asm("mov.b64 %0, {%1,%2};" : "=l"(r) : "f"(x), "r"(t));
    return r;
}
#define FMA2(acc, a, b) \
    asm("fma.rn.f32x2 %0, %1, %2, %0;" : "+l"(acc) : "l"(a), "l"(b))

__device__ __forceinline__ float sigf(float x) {
    return 1.0f / (1.0f + __expf(-x));
}
__device__ __forceinline__ float tanhfast(float x) {
    float ax = fabsf(x);
    float e  = __expf(-2.0f * ax);          // in (0,1], overflow-free
    float t  = __fdividef(1.0f - e, 1.0f + e);
    return copysignf(t, x);
}

// ---------------------------------------------------------------------------
// Kernel 0: reset state between graph replays (determinism requirement)
// slot 0 gets tag 0 / h = 0  ->  step-0 poll passes immediately with h_0 = 0.
// ---------------------------------------------------------------------------
__global__ void reset_kernel() {
    int i = threadIdx.x;
    if (i < H) { g_hq[0][i] = 0ull; g_hq[1][i] = 0ull; }
}

// ---------------------------------------------------------------------------
// Kernel 1: persistent fused LSTM recurrence (input GEMM folded in).
// 128 CTAs x 256 threads, 1 CTA/SM (register bound). Warp w of CTA b owns
// hidden unit u = b*8 + w (gate rows u, H+u, 2H+u, 3H+u).
// Lane l holds W_hh column pairs (2l+64k) k=0..15 (64 packed f32x2) plus
// W_ih column pair 2l (4 packed f32x2) in registers for all 4096 steps.
//
// Per-step protocol (ONE __syncthreads, zero fences):
//   1. prefetch x_{t+1} (tid<16, 256 B, triple-buffered SMEM)
//   2. poll: each thread spins on its 4 g_hq entries with four SCALAR
//      ld.relaxed.gpu.b64 (atomic) until all tags == t
//      -> tag and data arrive in the same L2 round trip
//   3. extract h -> hs[t&1] (STS.128), __syncthreads
//   4. matvec (LDS.64 + FMA2, W_hh + W_ih terms) -> shfl reduce -> gates
//   5. lane 0 publishes {h_new, t+1} into slot (t+1)&1 via
//      st.relaxed.gpu.b64 — that single atomic store IS the release
//      (tag carries the data with it); no trailing barrier.
//
// Overwrite safety: a CTA writes slot (t+1)&1 (= slot (t-1)&1) only during
// step t, which it enters only after observing all 1024 tag-t entries; every
// CTA's tag-t publish is data-dependent on its completed step t-1 poll reads
// of slot (t-1)&1. So a slot is clobbered only after all readers are done.
// Bar-phase alignment: a warp passes poll t+1 only after every warp of its
// own CTA published tag t+1 (post-step-t-bar), so all warps always meet at
// the same dynamic __syncthreads instance; intra-CTA skew < 1 step ->
// hs double-buffer and xs triple-buffer suffice.
// ---------------------------------------------------------------------------
__global__ void __launch_bounds__(256, 1) rec_kernel(
    const float* __restrict__ x,
    const float* __restrict__ Wih,
    const float* __restrict__ Whh,
    const float* __restrict__ bih,
    const float* __restrict__ bhh)
{
    __shared__ __align__(16) float hs[2][H];     // staged h_t
    __shared__ __align__(16) float xs[3][II];    // staged x_t (triple buffer)

    const int tid  = threadIdx.x;
    const int lane = tid & 31;
    const int wrp  = tid >> 5;               // 0..7
    const int u    = blockIdx.x * UPC + wrp; // hidden unit 0..1023

    // ---- W_hh slice into registers (coalesced float2 loads) ----
    unsigned long long wq[4][16];
    #pragma unroll
    for (int g = 0; g < 4; g++) {
        const float2* base = (const float2*)(Whh + (size_t)(g * H + u) * H) + lane;
        #pragma unroll
        for (int k = 0; k < 16; k++) {
            float2 v = base[k * 32];
            wq[g][k] = pk2(v.x, v.y);
        }
    }
    // ---- W_ih slice (cols 2l, 2l+1 of rows u, H+u, 2H+u, 3H+u) ----
    unsigned long long wx[4];
    #pragma unroll
    for (int g = 0; g < 4; g++) {
        float2 v = ((const float2*)(Wih + (size_t)(g * H + u) * II))[lane];
        wx[g] = pk2(v.x, v.y);
    }
    // ---- biases (only lane 0 consumes them) ----
    float bs0 = bih[u]         + bhh[u];
    float bs1 = bih[H + u]     + bhh[H + u];
    float bs2 = bih[2 * H + u] + bhh[2 * H + u];
    float bs3 = bih[3 * H + u] + bhh[3 * H + u];

    // ---- preload x_0 into xs[0] ----
    if (tid < 16) ((float4*)xs[0])[tid] = ((const float4*)x)[tid];
    __syncthreads();

    float c = 0.0f;                          // cell state (lane 0 only)
    const unsigned full = 0xffffffffu;

    const unsigned long long* mypoll = &g_hq[0][0] + 4 * tid;  // + slot*H per step

    #pragma unroll 1
    for (int t = 0; t < S; t++) {
        const int cur = t & 1;

        // 1. prefetch next step's input row (DRAM, hidden behind this step)
        if (t + 1 < S && tid < 16)
            ((float4*)xs[(t + 1) % 3])[tid] =
                __ldcg((const float4*)(x + (size_t)(t + 1) * II) + tid);

        // 2. poll own 4 h entries with ATOMIC relaxed b64 loads until tags == t
        const unsigned long long* p = mypoll + (size_t)cur * H;
        unsigned long long q0, q1, q2, q3;
        do {
            asm volatile("ld.relaxed.gpu.global.b64 %0, [%1];" : "=l"(q0) : "l"(p));
            asm volatile("ld.relaxed.gpu.global.b64 %0, [%1];" : "=l"(q1) : "l"(p + 1));
            asm volatile("ld.relaxed.gpu.global.b64 %0, [%1];" : "=l"(q2) : "l"(p + 2));
            asm volatile("ld.relaxed.gpu.global.b64 %0, [%1];" : "=l"(q3) : "l"(p + 3));
        } while ((unsigned)(q0 >> 32) != (unsigned)t ||
                 (unsigned)(q1 >> 32) != (unsigned)t ||
                 (unsigned)(q2 >> 32) != (unsigned)t ||
                 (unsigned)(q3 >> 32) != (unsigned)t);

        // 3. stage into SMEM
        float4 hv4;
        hv4.x = __uint_as_float((unsigned)q0);
        hv4.y = __uint_as_float((unsigned)q1);
        hv4.z = __uint_as_float((unsigned)q2);
        hv4.w = __uint_as_float((unsigned)q3);
        ((float4*)hs[cur])[tid] = hv4;
        __syncthreads();

        // 4. mat-vec: W_hh * h_t  +  W_ih * x_t  (all packed f32x2)
        unsigned long long a0 = 0ull, a1 = 0ull, a2 = 0ull, a3 = 0ull;
        const unsigned long long* h2p = (const unsigned long long*)hs[cur] + lane;
        #pragma unroll
        for (int k = 0; k < 16; k++) {
            unsigned long long hv = h2p[k * 32];
            FMA2(a0, wq[0][k], hv);
            FMA2(a1, wq[1][k], hv);
            FMA2(a2, wq[2][k], hv);
            FMA2(a3, wq[3][k], hv);
        }
        {
            unsigned long long xv = ((const unsigned long long*)xs[t % 3])[lane];
            FMA2(a0, wx[0], xv);
            FMA2(a1, wx[1], xv);
            FMA2(a2, wx[2], xv);
            FMA2(a3, wx[3], xv);
        }
        float s0, s1, s2, s3, xl, xh;
        upk2(a0, xl, xh); s0 = xl + xh;
        upk2(a1, xl, xh); s1 = xl + xh;
        upk2(a2, xl, xh); s2 = xl + xh;
        upk2(a3, xl, xh); s3 = xl + xh;

        #pragma unroll
        for (int off = 16; off > 0; off >>= 1) {
            s0 += __shfl_xor_sync(full, s0, off);
            s1 += __shfl_xor_sync(full, s1, off);
            s2 += __shfl_xor_sync(full, s2, off);
            s3 += __shfl_xor_sync(full, s3, off);
        }

        // 5. activations + publish (lane 0) — atomic relaxed STG.64 release
        if (lane == 0) {
            const float i_ = sigf(s0 + bs0);
            const float f_ = sigf(s1 + bs1);
            const float g_ = tanhfast(s2 + bs2);
            const float o_ = sigf(s3 + bs3);
            c = fmaf(f_, c, i_ * g_);
            const float hnew = o_ * tanhfast(c);
            unsigned long long pub = pk_fu(hnew, (unsigned)(t + 1));
            asm volatile("st.relaxed.gpu.global.b64 [%0], %1;"
                         :: "l"(&g_hq[(t + 1) & 1][u]), "l"(pub));
        }
        // no trailing bar: next iteration's extraction bar re-aligns warps
    }
}

// ---------------------------------------------------------------------------
// Kernel 2: out = h_S @ W_lin^T + b_lin   (O = 1)
// h_S lives in g_hq[S & 1] = g_hq[0] (tag field ignored)
// ---------------------------------------------------------------------------
__global__ void __launch_bounds__(1024) out_kernel(
    const float* __restrict__ Wlin,
    const float* __restrict__ blin,
    float* __restrict__ out)
{
    __shared__ float red[32];
    const int tid = threadIdx.x;
    float h = __uint_as_float((unsigned)(g_hq[0][tid] & 0xffffffffull));
    float v = h * Wlin[tid];
    #pragma unroll
    for (int off = 16; off > 0; off >>= 1)
        v += __shfl_xor_sync(0xffffffffu, v, off);
    if ((tid & 31) == 0) red[tid >> 5] = v;
    __syncthreads();
    if (tid < 32) {
        float xv = red[tid];
        #pragma unroll
        for (int off = 16; off > 0; off >>= 1)
            xv += __shfl_xor_sync(0xffffffffu, xv, off);
        if (tid == 0) out[0] = xv + blin[0];
    }
}

// ---------------------------------------------------------------------------
// kernel_launch (graph-capturable: plain launches only)
// Input order: input_seq, W_ih, W_hh, b_ih, b_hh, W_lin, b_lin (all fp32)
// ---------------------------------------------------------------------------
extern "C" void kernel_launch(void* const* d_in, const int* in_sizes, int n_in,
                              void* d_out, int out_size)
{
    const float* x    = (const float*)d_in[0];
    const float* Wih  = (const float*)d_in[1];
    const float* Whh  = (const float*)d_in[2];
    const float* bih  = (const float*)d_in[3];
    const float* bhh  = (const float*)d_in[4];
    const float* Wlin = (const float*)d_in[5];
    const float* blin = (const float*)d_in[6];
    float* out = (float*)d_out;

    reset_kernel<<<1, 1024>>>();
    rec_kernel<<<NCTA, 256>>>(x, Wih, Whh, bih, bhh);
    out_kernel<<<1, 1024>>>(Wlin, blin, out);
}

// round 8
// speedup vs baseline: 2.4579x; 2.4579x over previous
#include <cuda_runtime.h>
#include <cstdint>

// Problem sizes
#define S    4096
#define II   64
#define H    1024
#define NCTA 128
#define UPC  8        // hidden units per CTA (1 per warp, 8 warps)

// ---------------------------------------------------------------------------
// Device-global scratch (allocation-free rule: __device__ arrays only)
//
// g_hq: double-buffered hidden state, one 8-byte atom per unit:
//       low 32 bits = h value (f32 bits), high 32 bits = step tag.
//       h_t (input of step t) lives in slot t&1 with tag == t.
//       All accesses st/ld.relaxed.gpu.b64 (morally strong <=64b => single-
//       copy atomic; weak .cg tore tag/data apart — the R5/R6 bug).
//
// g_cnt: monotonic step counter, a HINT that gates the heavy tagged sweep.
//       Correctness never depends on it (tags self-validate); it exists to
//       keep 32K pollers from saturating LTS with 131K-req sweeps (the R7
//       perf bug). Only 1 thread/CTA spins on it (128 same-line loads/iter).
// ---------------------------------------------------------------------------
__device__ unsigned long long g_hq[2][H];
__device__ unsigned g_cnt;

// ---------------------------------------------------------------------------
// Helpers
// ---------------------------------------------------------------------------
__device__ __forceinline__ unsigned long long pk2(float x, float y) {
    unsigned long long r;
    asm("mov.b64 %0, {%1,%2};" : "=l"(r) : "f"(x), "f"(y));
    return r;
}
__device__ __forceinline__ void upk2(unsigned long long a, float& x, float& y) {
    asm("mov.b64 {%0,%1}, %2;" : "=f"(x), "=f"(y) : "l"(a));
}
__device__ __forceinline__ unsigned long long pk_fu(float x, unsigned t) {
    unsigned long long r;
    asm("mov.b64 %0, {%1,%2};" : "=l"(r) : "f"(x), "r"(t));
    return r;
}
#define FMA2(acc, a, b) \
    asm("fma.rn.f32x2 %0, %1, %2, %0;" : "+l"(acc) : "l"(a), "l"(b))

__device__ __forceinline__ float sigf(float x) {
    return 1.0f / (1.0f + __expf(-x));
}
__device__ __forceinline__ float tanhfast(float x) {
    float ax = fabsf(x);
    float e  = __expf(-2.0f * ax);          // in (0,1], overflow-free
    float t  = __fdividef(1.0f - e, 1.0f + e);
    return copysignf(t, x);
}

// ---------------------------------------------------------------------------
// Kernel 0: reset state between graph replays (determinism requirement)
// slot 0 gets tag 0 / h = 0  ->  step-0 sweep passes immediately with h_0 = 0.
// ---------------------------------------------------------------------------
__global__ void reset_kernel() {
    int i = threadIdx.x;
    if (i < H) { g_hq[0][i] = 0ull; g_hq[1][i] = 0ull; }
    if (i == 0) g_cnt = 0u;
}

// ---------------------------------------------------------------------------
// Kernel 1: persistent fused LSTM recurrence (input GEMM folded in).
// 128 CTAs x 256 threads, 1 CTA/SM (register bound). Warp w of CTA b owns
// hidden unit u = b*8 + w (gate rows u, H+u, 2H+u, 3H+u).
// Lane l holds W_hh column pairs (2l+64k) k=0..15 (64 packed f32x2) plus
// W_ih column pair 2l (4 packed f32x2) in registers for all 4096 steps.
//
// Per-step protocol:
//   1. prefetch x_{t+1} (tid<16, 256 B, triple-buffered SMEM)
//   2. GATE: tid 0 spins ld.relaxed on g_cnt until >= 128*t  (cheap: 128
//      same-line reqs/iter chip-wide), then __syncthreads releases the CTA
//   3. SWEEP: each thread reads its 4 tagged atoms (scalar ld.relaxed.b64),
//      retries in the (rare) case a tag is stale -> tag+data one L2 RT
//   4. stage h -> hs[t&1], __syncthreads
//   5. matvec (LDS.64 + FMA2, W_hh + W_ih) -> shfl reduce -> activations
//   6. lane 0 of each warp publishes {h_new, t+1} (st.relaxed.gpu.b64)
//   7. __syncthreads (keeps the hint honest), tid 0: red.add.relaxed g_cnt,1
//
// Overwrite safety (unchanged from R7, proven correct): a CTA writes slot
// (t+1)&1 only during step t, entered only after observing all 1024 tag-t
// atoms, and every CTA's tag-t publish postdates its own completed reads of
// slot (t-1)&1. Counter is advisory only; a spurious early gate-pass merely
// causes sweep retries.
// ---------------------------------------------------------------------------
__global__ void __launch_bounds__(256, 1) rec_kernel(
    const float* __restrict__ x,
    const float* __restrict__ Wih,
    const float* __restrict__ Whh,
    const float* __restrict__ bih,
    const float* __restrict__ bhh)
{
    __shared__ __align__(16) float hs[2][H];     // staged h_t
    __shared__ __align__(16) float xs[3][II];    // staged x_t (triple buffer)

    const int tid  = threadIdx.x;
    const int lane = tid & 31;
    const int wrp  = tid >> 5;               // 0..7
    const int u    = blockIdx.x * UPC + wrp; // hidden unit 0..1023

    // ---- W_hh slice into registers (coalesced float2 loads) ----
    unsigned long long wq[4][16];
    #pragma unroll
    for (int g = 0; g < 4; g++) {
        const float2* base = (const float2*)(Whh + (size_t)(g * H + u) * H) + lane;
        #pragma unroll
        for (int k = 0; k < 16; k++) {
            float2 v = base[k * 32];
            wq[g][k] = pk2(v.x, v.y);
        }
    }
    // ---- W_ih slice (cols 2l, 2l+1 of rows u, H+u, 2H+u, 3H+u) ----
    unsigned long long wx[4];
    #pragma unroll
    for (int g = 0; g < 4; g++) {
        float2 v = ((const float2*)(Wih + (size_t)(g * H + u) * II))[lane];
        wx[g] = pk2(v.x, v.y);
    }
    // ---- biases (only lane 0 consumes them) ----
    float bs0 = bih[u]         + bhh[u];
    float bs1 = bih[H + u]     + bhh[H + u];
    float bs2 = bih[2 * H + u] + bhh[2 * H + u];
    float bs3 = bih[3 * H + u] + bhh[3 * H + u];

    // ---- preload x_0 into xs[0] ----
    if (tid < 16) ((float4*)xs[0])[tid] = ((const float4*)x)[tid];
    __syncthreads();

    float c = 0.0f;                          // cell state (lane 0 only)
    const unsigned full = 0xffffffffu;

    const unsigned long long* mypoll = &g_hq[0][0] + 4 * tid;  // + slot*H per step

    #pragma unroll 1
    for (int t = 0; t < S; t++) {
        const int cur = t & 1;

        // 1. prefetch next step's input row (DRAM, hidden behind this step)
        if (t + 1 < S && tid < 16)
            ((float4*)xs[(t + 1) % 3])[tid] =
                __ldcg((const float4*)(x + (size_t)(t + 1) * II) + tid);

        // 2. GATE: single poller per CTA on the advisory counter
        if (t > 0 && tid == 0) {
            const unsigned need = (unsigned)t * NCTA;
            unsigned v;
            do {
                asm volatile("ld.relaxed.gpu.global.u32 %0, [%1];"
                             : "=r"(v) : "l"(&g_cnt));
            } while (v < need);
        }
        __syncthreads();

        // 3. SWEEP: 4 tagged atoms per thread; retry only if a tag is stale
        const unsigned long long* p = mypoll + (size_t)cur * H;
        unsigned long long q0, q1, q2, q3;
        do {
            asm volatile("ld.relaxed.gpu.global.b64 %0, [%1];" : "=l"(q0) : "l"(p));
            asm volatile("ld.relaxed.gpu.global.b64 %0, [%1];" : "=l"(q1) : "l"(p + 1));
            asm volatile("ld.relaxed.gpu.global.b64 %0, [%1];" : "=l"(q2) : "l"(p + 2));
            asm volatile("ld.relaxed.gpu.global.b64 %0, [%1];" : "=l"(q3) : "l"(p + 3));
        } while ((unsigned)(q0 >> 32) != (unsigned)t ||
                 (unsigned)(q1 >> 32) != (unsigned)t ||
                 (unsigned)(q2 >> 32) != (unsigned)t ||
                 (unsigned)(q3 >> 32) != (unsigned)t);

        // 4. stage into SMEM
        float4 hv4;
        hv4.x = __uint_as_float((unsigned)q0);
        hv4.y = __uint_as_float((unsigned)q1);
        hv4.z = __uint_as_float((unsigned)q2);
        hv4.w = __uint_as_float((unsigned)q3);
        ((float4*)hs[cur])[tid] = hv4;
        __syncthreads();

        // 5. mat-vec: W_hh * h_t  +  W_ih * x_t  (all packed f32x2)
        unsigned long long a0 = 0ull, a1 = 0ull, a2 = 0ull, a3 = 0ull;
        const unsigned long long* h2p = (const unsigned long long*)hs[cur] + lane;
        #pragma unroll
        for (int k = 0; k < 16; k++) {
            unsigned long long hv = h2p[k * 32];
            FMA2(a0, wq[0][k], hv);
            FMA2(a1, wq[1][k], hv);
            FMA2(a2, wq[2][k], hv);
            FMA2(a3, wq[3][k], hv);
        }
        {
            unsigned long long xv = ((const unsigned long long*)xs[t % 3])[lane];
            FMA2(a0, wx[0], xv);
            FMA2(a1, wx[1], xv);
            FMA2(a2, wx[2], xv);
            FMA2(a3, wx[3], xv);
        }
        float s0, s1, s2, s3, xl, xh;
        upk2(a0, xl, xh); s0 = xl + xh;
        upk2(a1, xl, xh); s1 = xl + xh;
        upk2(a2, xl, xh); s2 = xl + xh;
        upk2(a3, xl, xh); s3 = xl + xh;

        #pragma unroll
        for (int off = 16; off > 0; off >>= 1) {
            s0 += __shfl_xor_sync(full, s0, off);
            s1 += __shfl_xor_sync(full, s1, off);
            s2 += __shfl_xor_sync(full, s2, off);
            s3 += __shfl_xor_sync(full, s3, off);
        }

        // 6. activations + publish (lane 0 of each warp)
        if (lane == 0) {
            const float i_ = sigf(s0 + bs0);
            const float f_ = sigf(s1 + bs1);
            const float g_ = tanhfast(s2 + bs2);
            const float o_ = sigf(s3 + bs3);
            c = fmaf(f_, c, i_ * g_);
            const float hnew = o_ * tanhfast(c);
            unsigned long long pub = pk_fu(hnew, (unsigned)(t + 1));
            asm volatile("st.relaxed.gpu.global.b64 [%0], %1;"
                         :: "l"(&g_hq[(t + 1) & 1][u]), "l"(pub));
        }

        // 7. advisory counter bump (after all 8 warps issued their publish)
        __syncthreads();
        if (tid == 0)
            asm volatile("red.relaxed.gpu.global.add.u32 [%0], %1;"
                         :: "l"(&g_cnt), "r"(1u));
    }
}

// ---------------------------------------------------------------------------
// Kernel 2: out = h_S @ W_lin^T + b_lin   (O = 1)
// h_S lives in g_hq[S & 1] = g_hq[0] (tag field ignored)
// ---------------------------------------------------------------------------
__global__ void __launch_bounds__(1024) out_kernel(
    const float* __restrict__ Wlin,
    const float* __restrict__ blin,
    float* __restrict__ out)
{
    __shared__ float red[32];
    const int tid = threadIdx.x;
    float h = __uint_as_float((unsigned)(g_hq[0][tid] & 0xffffffffull));
    float v = h * Wlin[tid];
    #pragma unroll
    for (int off = 16; off > 0; off >>= 1)
        v += __shfl_xor_sync(0xffffffffu, v, off);
    if ((tid & 31) == 0) red[tid >> 5] = v;
    __syncthreads();
    if (tid < 32) {
        float xv = red[tid];
        #pragma unroll
        for (int off = 16; off > 0; off >>= 1)
            xv += __shfl_xor_sync(0xffffffffu, xv, off);
        if (tid == 0) out[0] = xv + blin[0];
    }
}

// ---------------------------------------------------------------------------
// kernel_launch (graph-capturable: plain launches only)
// Input order: input_seq, W_ih, W_hh, b_ih, b_hh, W_lin, b_lin (all fp32)
// ---------------------------------------------------------------------------
extern "C" void kernel_launch(void* const* d_in, const int* in_sizes, int n_in,
                              void* d_out, int out_size)
{
    const float* x    = (const float*)d_in[0];
    const float* Wih  = (const float*)d_in[1];
    const float* Whh  = (const float*)d_in[2];
    const float* bih  = (const float*)d_in[3];
    const float* bhh  = (const float*)d_in[4];
    const float* Wlin = (const float*)d_in[5];
    const float* blin = (const float*)d_in[6];
    float* out = (float*)d_out;

    reset_kernel<<<1, 1024>>>();
    rec_kernel<<<NCTA, 256>>>(x, Wih, Whh, bih, bhh);
    out_kernel<<<1, 1024>>>(Wlin, blin, out);
}